// round 8
// baseline (speedup 1.0000x reference)
#include <cuda_runtime.h>

// RNNModel: 2-layer tanh RNN + FC, B=2048, T=512, I=8, H=64.
// R7: warp-specialized teams. Block = 96 threads = 3 warps = 1 element.
//  - Warp 0: layer-0 recurrence SOLO (rows 2l,2l+1 of W_hh0 full-k in regs).
//    Barrier-free: same-warp SMEM recurrence with __syncwarp. No shfl reduce.
//  - Warps 1,2: layer-1, j-split (1 row/lane of W_ih1 + W_hh1 full-k in regs).
//    Pair exchanges h1 via 64-thread named barrier once per step.
//  - Layer 1 lags 4 steps behind layer 0 through a 2-bank x 4-slot h0 ring;
//    block-wide __syncthreads only once per 4 steps (bank handoff).
//  - All SMEM h reads are warp-broadcast LDS.128 (conflict-free).

#define TT 512
#define SS 4                 // steps per superstep (ring slots per bank)
#define NSS (TT / SS)        // 128 supersteps
#define HH 64
#define NTHREADS 96
#define BB 2048
#define FULLMASK 0xffffffffu

typedef unsigned long long ull;

__device__ __forceinline__ ull ffma2(ull a, ull b, ull c) {
    ull d; asm("fma.rn.f32x2 %0, %1, %2, %3;" : "=l"(d) : "l"(a), "l"(b), "l"(c)); return d;
}
__device__ __forceinline__ ull fadd2(ull a, ull b) {
    ull d; asm("add.rn.f32x2 %0, %1, %2;" : "=l"(d) : "l"(a), "l"(b)); return d;
}
__device__ __forceinline__ float hsum4(ull a0, ull a1, ull a2, ull a3) {
    ull s = fadd2(fadd2(a0, a1), fadd2(a2, a3));
    float2 f; asm("mov.b64 {%0, %1}, %2;" : "=f"(f.x), "=f"(f.y) : "l"(s));
    return f.x + f.y;
}
__device__ __forceinline__ float fast_tanh(float x) {
    // tanh(x) = 1 - 2/(exp(2x)+1); ex2 limits give exactly +-1, no clamp needed.
    float e; asm("ex2.approx.f32 %0, %1;" : "=f"(e) : "f"(x * 2.8853900817779268f));
    float r; asm("rcp.approx.f32 %0, %1;" : "=f"(r) : "f"(e + 1.f));
    return fmaf(-2.f, r, 1.f);
}

__global__ void __launch_bounds__(NTHREADS)
rnn_ws_kernel(const float* __restrict__ x,
              const float* __restrict__ W_ih0,
              const float* __restrict__ W_hh0,
              const float* __restrict__ b_ih0,
              const float* __restrict__ b_hh0,
              const float* __restrict__ W_ih1,
              const float* __restrict__ W_hh1,
              const float* __restrict__ b_ih1,
              const float* __restrict__ b_hh1,
              const float* __restrict__ fc_w,
              const float* __restrict__ fc_b,
              float* __restrict__ out)
{
    __shared__ __align__(16) float ring[2][SS][HH];  // h0 ring: [bank][slot][j]
    __shared__ __align__(16) float h1d[2][HH];       // h1 double buffer [t&1][j]
    __shared__ float sfc[2];

    const int tid  = threadIdx.x;
    const int wid  = tid >> 5;
    const int lane = tid & 31;
    const int e    = blockIdx.x;

    // h0[-1] = 0 (bank 1, slot SS-1) and h1[-1] = 0 (buffer 1).
    if (tid < HH) { ring[1][SS - 1][tid] = 0.f; h1d[1][tid] = 0.f; }
    __syncthreads();

    if (wid == 0) {
        // ================= Layer-0 producer (solo warp) =================
        const int j0 = 2 * lane, j1 = 2 * lane + 1;
        ull wA[32], wB[32], wI[8];
        {
            const ulonglong2* p = (const ulonglong2*)(W_hh0 + j0 * HH);
            #pragma unroll
            for (int i = 0; i < 16; i++) { ulonglong2 v = p[i]; wA[2*i] = v.x; wA[2*i+1] = v.y; }
        }
        {
            const ulonglong2* p = (const ulonglong2*)(W_hh0 + j1 * HH);
            #pragma unroll
            for (int i = 0; i < 16; i++) { ulonglong2 v = p[i]; wB[2*i] = v.x; wB[2*i+1] = v.y; }
        }
        {
            const ulonglong2* p = (const ulonglong2*)(W_ih0 + j0 * 8);  // rows j0,j1 = 16 floats
            #pragma unroll
            for (int i = 0; i < 4; i++) { ulonglong2 v = p[i]; wI[2*i] = v.x; wI[2*i+1] = v.y; }
        }
        const float b0a = b_ih0[j0] + b_hh0[j0];
        const float b0b = b_ih0[j1] + b_hh0[j1];
        const ulonglong2* __restrict__ xp = (const ulonglong2*)(x + (size_t)e * TT * 8);

        for (int s = 0; s <= NSS; s++) {
            if (s < NSS) {
                const int b = s & 1;
                #pragma unroll
                for (int i = 0; i < SS; i++) {
                    const int t = SS * s + i;
                    // x for this step (issued first; consumed after the q-loop).
                    ulonglong2 xa = xp[2 * t], xb = xp[2 * t + 1];
                    const float* hprev = (i == 0) ? ring[b ^ 1][SS - 1] : ring[b][i - 1];
                    const ulonglong2* hp = (const ulonglong2*)hprev;
                    ull a0 = 0, a1 = 0, a2 = 0, a3 = 0;   // row j0
                    ull c0 = 0, c1 = 0, c2 = 0, c3 = 0;   // row j1
                    #pragma unroll
                    for (int q = 0; q < 16; q++) {
                        ulonglong2 hv = hp[q];
                        if ((q & 1) == 0) {
                            a0 = ffma2(hv.x, wA[2*q], a0); a1 = ffma2(hv.y, wA[2*q+1], a1);
                            c0 = ffma2(hv.x, wB[2*q], c0); c1 = ffma2(hv.y, wB[2*q+1], c1);
                        } else {
                            a2 = ffma2(hv.x, wA[2*q], a2); a3 = ffma2(hv.y, wA[2*q+1], a3);
                            c2 = ffma2(hv.x, wB[2*q], c2); c3 = ffma2(hv.y, wB[2*q+1], c3);
                        }
                    }
                    // x-term (8 FFMA2) merged into the accumulators.
                    a0 = ffma2(xa.x, wI[0], a0); a1 = ffma2(xa.y, wI[1], a1);
                    a2 = ffma2(xb.x, wI[2], a2); a3 = ffma2(xb.y, wI[3], a3);
                    c0 = ffma2(xa.x, wI[4], c0); c1 = ffma2(xa.y, wI[5], c1);
                    c2 = ffma2(xb.x, wI[6], c2); c3 = ffma2(xb.y, wI[7], c3);

                    float h0a = fast_tanh(b0a + hsum4(a0, a1, a2, a3));
                    float h0b = fast_tanh(b0b + hsum4(c0, c1, c2, c3));
                    *(float2*)&ring[b][i][2 * lane] = make_float2(h0a, h0b);
                    __syncwarp();   // own store visible to whole warp next step
                }
            }
            __syncthreads();        // bank handoff to the layer-1 pair
        }
        __syncthreads();            // match FC epilogue sync
        if (tid == 0) out[e] = sfc[0] + sfc[1] + fc_b[0];
    } else {
        // ================= Layer-1 pair (warps 1 & 2) =================
        const int j = (wid - 1) * 32 + lane;
        ull u[32], v[32];
        {
            const ulonglong2* p = (const ulonglong2*)(W_ih1 + j * HH);
            #pragma unroll
            for (int i = 0; i < 16; i++) { ulonglong2 w = p[i]; u[2*i] = w.x; u[2*i+1] = w.y; }
        }
        {
            const ulonglong2* p = (const ulonglong2*)(W_hh1 + j * HH);
            #pragma unroll
            for (int i = 0; i < 16; i++) { ulonglong2 w = p[i]; v[2*i] = w.x; v[2*i+1] = w.y; }
        }
        const float bv1 = b_ih1[j] + b_hh1[j];
        const float fcw = fc_w[j];
        float h1n = 0.f;

        for (int s = 0; s <= NSS; s++) {
            if (s >= 1) {
                const int b = (s - 1) & 1;
                #pragma unroll
                for (int i = 0; i < SS; i++) {
                    const int t = SS * (s - 1) + i;
                    const int p = t & 1;
                    const ulonglong2* hp0 = (const ulonglong2*)ring[b][i];    // h0[t]
                    const ulonglong2* hp1 = (const ulonglong2*)h1d[p ^ 1];    // h1[t-1]
                    ull u0 = 0, u1 = 0, u2 = 0, u3 = 0;
                    ull v0 = 0, v1 = 0, v2 = 0, v3 = 0;
                    #pragma unroll
                    for (int q = 0; q < 16; q++) {
                        ulonglong2 hv = hp0[q];
                        ulonglong2 gv = hp1[q];
                        if ((q & 1) == 0) {
                            u0 = ffma2(hv.x, u[2*q], u0); u1 = ffma2(hv.y, u[2*q+1], u1);
                            v0 = ffma2(gv.x, v[2*q], v0); v1 = ffma2(gv.y, v[2*q+1], v1);
                        } else {
                            u2 = ffma2(hv.x, u[2*q], u2); u3 = ffma2(hv.y, u[2*q+1], u3);
                            v2 = ffma2(gv.x, v[2*q], v2); v3 = ffma2(gv.y, v[2*q+1], v3);
                        }
                    }
                    float s1 = hsum4(u0, u1, u2, u3) + hsum4(v0, v1, v2, v3);
                    h1n = fast_tanh(bv1 + s1);
                    h1d[p][j] = h1n;
                    asm volatile("bar.sync 1, 64;" ::: "memory");  // pair exchange
                }
            }
            __syncthreads();        // bank handoff from layer-0 warp
        }

        // FC partial: h1n holds h1[T-1][j].
        float vv = h1n * fcw;
        #pragma unroll
        for (int off = 16; off > 0; off >>= 1)
            vv += __shfl_xor_sync(FULLMASK, vv, off);
        if (lane == 0) sfc[wid - 1] = vv;
        __syncthreads();            // match producer's epilogue sync
    }
}

extern "C" void kernel_launch(void* const* d_in, const int* in_sizes, int n_in,
                              void* d_out, int out_size)
{
    const float* x     = (const float*)d_in[0];
    const float* W_ih0 = (const float*)d_in[1];
    const float* W_hh0 = (const float*)d_in[2];
    const float* b_ih0 = (const float*)d_in[3];
    const float* b_hh0 = (const float*)d_in[4];
    const float* W_ih1 = (const float*)d_in[5];
    const float* W_hh1 = (const float*)d_in[6];
    const float* b_ih1 = (const float*)d_in[7];
    const float* b_hh1 = (const float*)d_in[8];
    const float* fc_w  = (const float*)d_in[9];
    const float* fc_b  = (const float*)d_in[10];
    float* out = (float*)d_out;

    dim3 grid(BB);          // 2048 blocks, one batch element each
    dim3 block(NTHREADS);   // 96 threads = 3 warps (1 producer + 2 consumers)
    rnn_ws_kernel<<<grid, block>>>(
        x, W_ih0, W_hh0, b_ih0, b_hh0,
        W_ih1, W_hh1, b_ih1, b_hh1,
        fc_w, fc_b, out);
}

// round 9
// speedup vs baseline: 1.0017x; 1.0017x over previous
#include <cuda_runtime.h>

// RNNModel: 2-layer tanh RNN + FC, B=2048, T=512, I=8, H=64.
// R8: 4 warps/element split BY LAYER with full-row lanes (no shfl k-reduce).
//  - roles {0,1}: layer 0. lane -> row j of W_hh0 (full k, 64 regs) + W_ih0 row.
//  - roles {2,3}: layer 1. lane -> rows j of W_ih1 + W_hh1 (128 regs).
//  - role = (wid + bid) & 3 rotates heavy warps across SMSPs between blocks.
//  - Lag-1 pipeline (layer 1 computes h1[i-1] at step i) -> ONE bar/step.
//  - Each lane finishes its h[j] in-register: no shfl, one tanh per lane.
//  - __launch_bounds__(128,3): <=170 regs -> 3 blocks/SM = 12 warps.

#define TT 512
#define HH 64
#define NTHREADS 128
#define BB 2048
#define FULLMASK 0xffffffffu

typedef unsigned long long ull;

__device__ __forceinline__ ull ffma2(ull a, ull b, ull c) {
    ull d; asm("fma.rn.f32x2 %0, %1, %2, %3;" : "=l"(d) : "l"(a), "l"(b), "l"(c)); return d;
}
__device__ __forceinline__ ull fadd2(ull a, ull b) {
    ull d; asm("add.rn.f32x2 %0, %1, %2;" : "=l"(d) : "l"(a), "l"(b)); return d;
}
__device__ __forceinline__ float hsum4(ull a0, ull a1, ull a2, ull a3) {
    ull s = fadd2(fadd2(a0, a1), fadd2(a2, a3));
    float2 f; asm("mov.b64 {%0, %1}, %2;" : "=f"(f.x), "=f"(f.y) : "l"(s));
    return f.x + f.y;
}
__device__ __forceinline__ float fast_tanh(float x) {
    // tanh(x) = 1 - 2/(exp(2x)+1); ex2 limits give exactly +-1, no clamp needed.
    float e; asm("ex2.approx.f32 %0, %1;" : "=f"(e) : "f"(x * 2.8853900817779268f));
    float r; asm("rcp.approx.f32 %0, %1;" : "=f"(r) : "f"(e + 1.f));
    return fmaf(-2.f, r, 1.f);
}

__global__ void __launch_bounds__(NTHREADS, 3)
rnn_roles_kernel(const float* __restrict__ x,
                 const float* __restrict__ W_ih0,
                 const float* __restrict__ W_hh0,
                 const float* __restrict__ b_ih0,
                 const float* __restrict__ b_hh0,
                 const float* __restrict__ W_ih1,
                 const float* __restrict__ W_hh1,
                 const float* __restrict__ b_ih1,
                 const float* __restrict__ b_hh1,
                 const float* __restrict__ fc_w,
                 const float* __restrict__ fc_b,
                 float* __restrict__ out)
{
    __shared__ __align__(16) float h0d[2][HH];   // h0 double buffer
    __shared__ __align__(16) float h1d[2][HH];   // h1 double buffer
    __shared__ float sfc[2];

    const int tid  = threadIdx.x;
    const int wid  = tid >> 5;
    const int lane = tid & 31;
    const int e    = blockIdx.x;
    const int role = (wid + e) & 3;              // rotate roles across blocks

    if (tid < HH) h1d[1][tid] = 0.f;             // h1[-1] = 0
    __syncthreads();                             // bar 0

    if (role < 2) {
        // ===================== Layer-0 warps =====================
        const int j = (role << 5) | lane;
        ull whh[32], wih[4];
        {
            const ulonglong2* p = (const ulonglong2*)(W_hh0 + j * HH);
            #pragma unroll
            for (int i = 0; i < 16; i++) { ulonglong2 v = p[i]; whh[2*i] = v.x; whh[2*i+1] = v.y; }
        }
        {
            const ulonglong2* p = (const ulonglong2*)(W_ih0 + j * 8);
            ulonglong2 v = p[0]; wih[0] = v.x; wih[1] = v.y;
            v = p[1];            wih[2] = v.x; wih[3] = v.y;
        }
        const float b0 = b_ih0[j] + b_hh0[j];
        const ulonglong2* __restrict__ xp = (const ulonglong2*)(x + (size_t)e * TT * 8);
        ulonglong2 xa = xp[0], xb = xp[1];

        // Peel i=0: h0[0] = tanh(b0 + x0.Wih0)  (h0[-1] = 0).
        {
            ull a0 = ffma2(xa.x, wih[0], 0ull);
            ull a1 = ffma2(xa.y, wih[1], 0ull);
            ull a2 = ffma2(xb.x, wih[2], 0ull);
            ull a3 = ffma2(xb.y, wih[3], 0ull);
            h0d[0][j] = fast_tanh(b0 + hsum4(a0, a1, a2, a3));
        }
        __syncthreads();                         // peel bar
        xa = xp[2]; xb = xp[3]; xp += 4;

#define STEP0(RD, WR, PF)                                                      \
        {                                                                      \
            ull a0 = ffma2(xa.x, wih[0], 0ull);                                \
            ull a1 = ffma2(xa.y, wih[1], 0ull);                                \
            ull a2 = ffma2(xb.x, wih[2], 0ull);                                \
            ull a3 = ffma2(xb.y, wih[3], 0ull);                                \
            ulonglong2 nxa, nxb;                                               \
            if (PF) { nxa = xp[0]; nxb = xp[1]; xp += 2; }                     \
            const ulonglong2* hp = (const ulonglong2*)(RD);                    \
            _Pragma("unroll")                                                  \
            for (int q = 0; q < 16; q++) {                                     \
                ulonglong2 hv = hp[q];                                         \
                if ((q & 1) == 0) {                                            \
                    a0 = ffma2(hv.x, whh[2*q], a0);                            \
                    a1 = ffma2(hv.y, whh[2*q+1], a1);                          \
                } else {                                                       \
                    a2 = ffma2(hv.x, whh[2*q], a2);                            \
                    a3 = ffma2(hv.y, whh[2*q+1], a3);                          \
                }                                                              \
            }                                                                  \
            (WR)[j] = fast_tanh(b0 + hsum4(a0, a1, a2, a3));                   \
            __syncthreads();                                                   \
            if (PF) { xa = nxa; xb = nxb; }                                    \
        }

        for (int iu = 0; iu < 255; iu++) {
            STEP0(h0d[0], h0d[1], 1);            // i odd
            STEP0(h0d[1], h0d[0], 1);            // i even
        }
        STEP0(h0d[0], h0d[1], 0);                // i = 511
#undef STEP0
    } else {
        // ===================== Layer-1 warps =====================
        const int j = ((role - 2) << 5) | lane;
        ull wu[32], wv[32];
        {
            const ulonglong2* p = (const ulonglong2*)(W_ih1 + j * HH);
            #pragma unroll
            for (int i = 0; i < 16; i++) { ulonglong2 w = p[i]; wu[2*i] = w.x; wu[2*i+1] = w.y; }
        }
        {
            const ulonglong2* p = (const ulonglong2*)(W_hh1 + j * HH);
            #pragma unroll
            for (int i = 0; i < 16; i++) { ulonglong2 w = p[i]; wv[2*i] = w.x; wv[2*i+1] = w.y; }
        }
        const float b1 = b_ih1[j] + b_hh1[j];
        const float fw = fc_w[j];
        float h1n = 0.f;
        __syncthreads();                         // matches peel bar

        // At step i: h1[i-1] = tanh(b1 + Wih1.h0[i-1] + Whh1.h1[i-2]).
#define STEP1(H0R, H1R, H1W)                                                   \
        {                                                                      \
            ull u0 = 0, u1 = 0, u2 = 0, u3 = 0;                                \
            ull v0 = 0, v1 = 0, v2 = 0, v3 = 0;                                \
            const ulonglong2* hp0 = (const ulonglong2*)(H0R);                  \
            const ulonglong2* hp1 = (const ulonglong2*)(H1R);                  \
            _Pragma("unroll")                                                  \
            for (int q = 0; q < 16; q++) {                                     \
                ulonglong2 av = hp0[q];                                        \
                ulonglong2 bv = hp1[q];                                        \
                if ((q & 1) == 0) {                                            \
                    u0 = ffma2(av.x, wu[2*q], u0); u1 = ffma2(av.y, wu[2*q+1], u1); \
                    v0 = ffma2(bv.x, wv[2*q], v0); v1 = ffma2(bv.y, wv[2*q+1], v1); \
                } else {                                                       \
                    u2 = ffma2(av.x, wu[2*q], u2); u3 = ffma2(av.y, wu[2*q+1], u3); \
                    v2 = ffma2(bv.x, wv[2*q], v2); v3 = ffma2(bv.y, wv[2*q+1], v3); \
                }                                                              \
            }                                                                  \
            float s = hsum4(u0, u1, u2, u3) + hsum4(v0, v1, v2, v3);           \
            h1n = fast_tanh(b1 + s);                                           \
            (H1W)[j] = h1n;                                                    \
            __syncthreads();                                                   \
        }

        for (int iu = 0; iu < 255; iu++) {
            STEP1(h0d[0], h1d[1], h1d[0]);       // i odd:  h1[i-1] (parity 0)
            STEP1(h0d[1], h1d[0], h1d[1]);       // i even: h1[i-1] (parity 1)
        }
        STEP1(h0d[0], h1d[1], h1d[0]);           // i = 511 -> h1[510]
#undef STEP1

        // Tail: h1[511] from h0[511] (h0d[1]) and h1[510] (h1d[0]).
        {
            ull u0 = 0, u1 = 0, u2 = 0, u3 = 0;
            ull v0 = 0, v1 = 0, v2 = 0, v3 = 0;
            const ulonglong2* hp0 = (const ulonglong2*)(h0d[1]);
            const ulonglong2* hp1 = (const ulonglong2*)(h1d[0]);
            #pragma unroll
            for (int q = 0; q < 16; q++) {
                ulonglong2 av = hp0[q];
                ulonglong2 bv = hp1[q];
                if ((q & 1) == 0) {
                    u0 = ffma2(av.x, wu[2*q], u0); u1 = ffma2(av.y, wu[2*q+1], u1);
                    v0 = ffma2(bv.x, wv[2*q], v0); v1 = ffma2(bv.y, wv[2*q+1], v1);
                } else {
                    u2 = ffma2(av.x, wu[2*q], u2); u3 = ffma2(av.y, wu[2*q+1], u3);
                    v2 = ffma2(bv.x, wv[2*q], v2); v3 = ffma2(bv.y, wv[2*q+1], v3);
                }
            }
            float s = hsum4(u0, u1, u2, u3) + hsum4(v0, v1, v2, v3);
            h1n = fast_tanh(b1 + s);
        }

        // FC partial over this warp's 32 j's.
        float v = h1n * fw;
        #pragma unroll
        for (int off = 16; off > 0; off >>= 1)
            v += __shfl_xor_sync(FULLMASK, v, off);
        if (lane == 0) sfc[role - 2] = v;
    }

    __syncthreads();                             // final bar (both branches)
    if (tid == 0)
        out[e] = sfc[0] + sfc[1] + fc_b[0];
}

extern "C" void kernel_launch(void* const* d_in, const int* in_sizes, int n_in,
                              void* d_out, int out_size)
{
    const float* x     = (const float*)d_in[0];
    const float* W_ih0 = (const float*)d_in[1];
    const float* W_hh0 = (const float*)d_in[2];
    const float* b_ih0 = (const float*)d_in[3];
    const float* b_hh0 = (const float*)d_in[4];
    const float* W_ih1 = (const float*)d_in[5];
    const float* W_hh1 = (const float*)d_in[6];
    const float* b_ih1 = (const float*)d_in[7];
    const float* b_hh1 = (const float*)d_in[8];
    const float* fc_w  = (const float*)d_in[9];
    const float* fc_b  = (const float*)d_in[10];
    float* out = (float*)d_out;

    dim3 grid(BB);          // 2048 blocks, one batch element each
    dim3 block(NTHREADS);   // 128 threads = 4 warps (2x layer-0, 2x layer-1)
    rnn_roles_kernel<<<grid, block>>>(
        x, W_ih0, W_hh0, b_ih0, b_hh0,
        W_ih1, W_hh1, b_ih1, b_hh1,
        fc_w, fc_b, out);
}